// round 8
// baseline (speedup 1.0000x reference)
#include <cuda_runtime.h>
#include <math.h>

// Problem constants (fixed by the dataset): B=256, K=512, D=1024
#define B_SZ 256
#define K_SZ 512
#define D_SZ 1024
#define INV_T (1.0f / 0.07f)

#define K_PER_BLOCK 8                      // 8 warps per block, one k per warp
#define BLOCKS_PER_B (K_SZ / K_PER_BLOCK)  // 64
#define NBLK (B_SZ * BLOCKS_PER_B)         // 16384

// Scratch (no cudaMalloc allowed; zero-initialized)
__device__ float g_fg_per_b[B_SZ];        // exp(fg_logit / T) per sample
__device__ float g_part[NBLK];            // per-block partial sums
__device__ float g_bsum[B_SZ];            // per-sample sums (stage 2)
__device__ unsigned g_cnt_b[B_SZ];        // per-sample arrival counters
__device__ unsigned g_cnt_all;            // global stage-2 counter

// one acq_rel atomic: release my prior writes, acquire everyone else's
__device__ __forceinline__ unsigned arrive_acq_rel(unsigned* ctr) {
    unsigned r;
    asm volatile("atom.acq_rel.gpu.global.add.u32 %0, [%1], %2;"
                 : "=r"(r) : "l"(ctr), "r"(1u) : "memory");
    return r;
}

// ---------------------------------------------------------------------------
// Single kernel. Streaming part = proven R2 structure (one k per warp, fast
// block exit). Tail reduction is hierarchical and overlapped:
//   stage 1: every block publishes g_part[blk], arrives at g_cnt_b[b]
//   stage 2: last-of-b block (1 warp) folds its 64 partials -> g_bsum[b]
//   stage 3: 256th stage-2 finisher folds 256 b-sums + 256 fg -> loss
// grid = 16384, block = 256
// ---------------------------------------------------------------------------
__global__ void __launch_bounds__(256) fused_kernel(
    const float* __restrict__ img,
    const float* __restrict__ fg,
    const float* __restrict__ pro,
    float* __restrict__ out)
{
    __shared__ float4 s_img[256];   // 4 KB: the img row
    __shared__ float  s_ss[8];
    __shared__ float  s_fg[8];
    __shared__ float  s_part[8];
    __shared__ int    s_lastb;
    __shared__ int    s_lastall;

    const int blk  = blockIdx.x;
    const int b    = blk >> 6;          // blk / BLOCKS_PER_B
    const int kgrp = blk & 63;          // blk % BLOCKS_PER_B
    const int t    = threadIdx.x;
    const int w    = t >> 5;
    const int l    = t & 31;

    // ---- load img row into smem + sum of squares ----
    float4 v = ((const float4*)(img + (size_t)b * D_SZ))[t];
    s_img[t] = v;

    float ss = v.x * v.x + v.y * v.y + v.z * v.z + v.w * v.w;
    #pragma unroll
    for (int o = 16; o > 0; o >>= 1)
        ss += __shfl_xor_sync(0xFFFFFFFFu, ss, o);
    if (l == 0) s_ss[w] = ss;
    if (t == 0) { s_lastall = 0; }
    __syncthreads();

    float tss = 0.f;
    #pragma unroll
    for (int i = 0; i < 8; i++) tss += s_ss[i];
    const float inv = 1.0f / sqrtf(tss);

    // ---- fg dot: only in the first block of each sample ----
    if (kgrp == 0) {
        float4 f = ((const float4*)(fg + (size_t)b * D_SZ))[t];
        float fd = v.x * f.x + v.y * f.y + v.z * f.z + v.w * f.w;
        #pragma unroll
        for (int o = 16; o > 0; o >>= 1)
            fd += __shfl_xor_sync(0xFFFFFFFFu, fd, o);
        if (l == 0) s_fg[w] = fd;
        __syncthreads();
        if (t == 0) {
            float tfd = 0.f;
            #pragma unroll
            for (int i = 0; i < 8; i++) tfd += s_fg[i];
            g_fg_per_b[b] = expf(tfd * inv * INV_T);   // ordered by release below
        }
    }

    // ---- each warp: one (b,k) dot, pro streamed from DRAM ----
    const int k = (kgrp << 3) + w;
    const float4* p4 = (const float4*)(pro + ((size_t)b * K_SZ + k) * D_SZ);

    float4 p[8];
    #pragma unroll
    for (int j = 0; j < 8; j++)
        p[j] = p4[j * 32 + l];              // 8 independent LDG.128

    float acc = 0.f;
    #pragma unroll
    for (int j = 0; j < 8; j++) {
        float4 a = s_img[j * 32 + l];
        acc += a.x * p[j].x + a.y * p[j].y + a.z * p[j].z + a.w * p[j].w;
    }

    #pragma unroll
    for (int o = 16; o > 0; o >>= 1)
        acc += __shfl_xor_sync(0xFFFFFFFFu, acc, o);
    if (l == 0) s_part[w] = expf(acc * inv * INV_T);
    __syncthreads();

    // ---- stage 1: publish partial, arrive at per-b counter ----
    if (t == 0) {
        float tsum = 0.f;
        #pragma unroll
        for (int i = 0; i < 8; i++) tsum += s_part[i];
        g_part[blk] = tsum;
        unsigned r = arrive_acq_rel(&g_cnt_b[b]);   // releases g_part (+ fg)
        s_lastb = (r == (unsigned)(BLOCKS_PER_B - 1));
    }
    __syncthreads();
    if (!s_lastb) return;                            // fast exit keeps streaming hot

    // ---- stage 2: last-of-b folds its 64 partials (warp 0 only) ----
    if (w == 0) {
        float a = g_part[(b << 6) + l] + g_part[(b << 6) + 32 + l];
        #pragma unroll
        for (int o = 16; o > 0; o >>= 1)
            a += __shfl_xor_sync(0xFFFFFFFFu, a, o);
        if (l == 0) {
            g_bsum[b] = a;
            g_cnt_b[b] = 0;                          // reset for next replay
            unsigned r2 = arrive_acq_rel(&g_cnt_all);
            s_lastall = (r2 == (unsigned)(B_SZ - 1));
        }
    }
    __syncthreads();
    if (!s_lastall) return;

    // ---- stage 3: final fold of 256 b-sums + 256 fg terms ----
    if (t == 0) g_cnt_all = 0;                       // reset for next replay

    double a2 = (double)g_bsum[t];                   // t in [0,256)
    double f2 = (double)g_fg_per_b[t];

    #pragma unroll
    for (int o = 16; o > 0; o >>= 1) {
        a2 += __shfl_xor_sync(0xFFFFFFFFu, a2, o);
        f2 += __shfl_xor_sync(0xFFFFFFFFu, f2, o);
    }

    __shared__ double sa[8];
    __shared__ double sfd[8];
    if (l == 0) { sa[w] = a2; sfd[w] = f2; }
    __syncthreads();

    if (t == 0) {
        double a = 0.0, f = 0.0;
        #pragma unroll
        for (int i = 0; i < 8; i++) { a += sa[i]; f += sfd[i]; }
        double pos = a / (double)K_SZ;               // sum_b mean_k exp(...)
        double neg = pos + f;
        out[0] = (float)(-log(pos / neg));
    }
}

// ---------------------------------------------------------------------------
extern "C" void kernel_launch(void* const* d_in, const int* in_sizes, int n_in,
                              void* d_out, int out_size)
{
    const float* img = (const float*)d_in[0];  // bg_img_feature [256,1024]
    const float* fg  = (const float*)d_in[1];  // fg_pro_feature [256,1024]
    const float* pro = (const float*)d_in[2];  // bg_pro_feature [256,512,1024]

    fused_kernel<<<NBLK, 256>>>(img, fg, pro, (float*)d_out);
}

// round 9
// speedup vs baseline: 1.1029x; 1.1029x over previous
#include <cuda_runtime.h>
#include <math.h>

// Problem constants (fixed by the dataset): B=256, K=512, D=1024
#define B_SZ 256
#define K_SZ 512
#define D_SZ 1024
#define INV_T (1.0f / 0.07f)

#define K_PER_BLOCK 8                      // 8 warps per block, one k per warp
#define BLOCKS_PER_B (K_SZ / K_PER_BLOCK)  // 64
#define NBLK (B_SZ * BLOCKS_PER_B)         // 16384

#define RBLK 64                            // reduce kernel blocks

// Scratch (no cudaMalloc allowed)
__device__ float g_fg_per_b[B_SZ];       // exp(fg_logit / T) per sample
__device__ float g_part[NBLK];           // per-block partial sums
__device__ float g_p2[RBLK];             // stage-2 partials
__device__ float g_f2[RBLK];             // stage-2 fg partials
__device__ unsigned int g_count2;        // stage-2 arrival counter (zero-init)

// ---------------------------------------------------------------------------
// Kernel A: the streamer (R2/R7 structure, __ldcs restored). Blocks signal
// PDL dependents as they finish so kernel B launches during the drain.
// grid = 16384, block = 256
// ---------------------------------------------------------------------------
__global__ void __launch_bounds__(256) fused_kernel(
    const float* __restrict__ img,
    const float* __restrict__ fg,
    const float* __restrict__ pro)
{
    __shared__ float4 s_img[256];   // 4 KB: the img row
    __shared__ float  s_ss[8];
    __shared__ float  s_fg[8];
    __shared__ float  s_part[8];

    const int blk  = blockIdx.x;
    const int b    = blk >> 6;          // blk / BLOCKS_PER_B
    const int kgrp = blk & 63;          // blk % BLOCKS_PER_B
    const int t    = threadIdx.x;
    const int w    = t >> 5;
    const int l    = t & 31;

    // ---- load img row into smem + sum of squares ----
    float4 v = ((const float4*)(img + (size_t)b * D_SZ))[t];
    s_img[t] = v;

    float ss = v.x * v.x + v.y * v.y + v.z * v.z + v.w * v.w;
    #pragma unroll
    for (int o = 16; o > 0; o >>= 1)
        ss += __shfl_xor_sync(0xFFFFFFFFu, ss, o);
    if (l == 0) s_ss[w] = ss;
    __syncthreads();

    float tss = 0.f;
    #pragma unroll
    for (int i = 0; i < 8; i++) tss += s_ss[i];
    const float inv = 1.0f / sqrtf(tss);

    // ---- fg dot: only in the first block of each sample ----
    if (kgrp == 0) {
        float4 f = ((const float4*)(fg + (size_t)b * D_SZ))[t];
        float fd = v.x * f.x + v.y * f.y + v.z * f.z + v.w * f.w;
        #pragma unroll
        for (int o = 16; o > 0; o >>= 1)
            fd += __shfl_xor_sync(0xFFFFFFFFu, fd, o);
        if (l == 0) s_fg[w] = fd;
        __syncthreads();
        if (t == 0) {
            float tfd = 0.f;
            #pragma unroll
            for (int i = 0; i < 8; i++) tfd += s_fg[i];
            g_fg_per_b[b] = expf(tfd * inv * INV_T);
        }
    }

    // ---- each warp: one (b,k) dot, pro streamed from DRAM ----
    const int k = (kgrp << 3) + w;
    const float4* p4 = (const float4*)(pro + ((size_t)b * K_SZ + k) * D_SZ);

    float4 p[8];
    #pragma unroll
    for (int j = 0; j < 8; j++)
        p[j] = __ldcs(p4 + j * 32 + l);     // 8 independent streaming LDG.128

    float acc = 0.f;
    #pragma unroll
    for (int j = 0; j < 8; j++) {
        float4 a = s_img[j * 32 + l];
        acc += a.x * p[j].x + a.y * p[j].y + a.z * p[j].z + a.w * p[j].w;
    }

    #pragma unroll
    for (int o = 16; o > 0; o >>= 1)
        acc += __shfl_xor_sync(0xFFFFFFFFu, acc, o);
    if (l == 0) s_part[w] = expf(acc * inv * INV_T);
    __syncthreads();

    if (t == 0) {
        float tsum = 0.f;
        #pragma unroll
        for (int i = 0; i < 8; i++) tsum += s_part[i];
        g_part[blk] = tsum;   // fixed order: deterministic across replays
        // PDL: this CTA is done — allow dependent grid to launch early.
        asm volatile("griddepcontrol.launch_dependents;");
    }
}

// ---------------------------------------------------------------------------
// Kernel B: grid-64 tree reduce, PDL-launched. Parks in griddepcontrol.wait
// until kernel A's memory is visible, then folds 16384 partials (L2-hot).
// grid = 64, block = 256
// ---------------------------------------------------------------------------
__global__ void __launch_bounds__(256) reduce_kernel(float* __restrict__ out)
{
    // Wait for the producer grid's completion + memory flush.
    asm volatile("griddepcontrol.wait;" ::: "memory");

    __shared__ double sa[8];
    __shared__ double sf[8];
    __shared__ int    s_last;

    const int j = blockIdx.x;
    const int t = threadIdx.x;
    const int w = t >> 5;
    const int l = t & 31;

    // ---- stage 1: 256 partials + 4 fg terms per block ----
    double a = (double)g_part[j * 256 + t];
    double f = (t < 4) ? (double)g_fg_per_b[j * 4 + t] : 0.0;

    #pragma unroll
    for (int o = 16; o > 0; o >>= 1) {
        a += __shfl_xor_sync(0xFFFFFFFFu, a, o);
        f += __shfl_xor_sync(0xFFFFFFFFu, f, o);
    }
    if (l == 0) { sa[w] = a; sf[w] = f; }
    __syncthreads();

    if (t == 0) {
        double ta = 0.0, tf = 0.0;
        #pragma unroll
        for (int i = 0; i < 8; i++) { ta += sa[i]; tf += sf[i]; }
        g_p2[j] = (float)ta;
        g_f2[j] = (float)tf;
        __threadfence();
        unsigned r = atomicAdd(&g_count2, 1u);
        s_last = (r == (unsigned)(RBLK - 1));
    }
    __syncthreads();
    if (!s_last) return;

    // ---- stage 2: last block folds 64 + 64 values ----
    if (t == 0) g_count2 = 0;                 // reset for next graph replay

    if (w < 2) {                              // 64 threads
        double a2 = (double)g_p2[t];
        double f2 = (double)g_f2[t];
        #pragma unroll
        for (int o = 16; o > 0; o >>= 1) {
            a2 += __shfl_xor_sync(0xFFFFFFFFu, a2, o);
            f2 += __shfl_xor_sync(0xFFFFFFFFu, f2, o);
        }
        if (l == 0) { sa[w] = a2; sf[w] = f2; }
    }
    __syncthreads();

    if (t == 0) {
        double pos = (sa[0] + sa[1]) / (double)K_SZ;  // sum_b mean_k exp(...)
        double neg = pos + (sf[0] + sf[1]);
        out[0] = (float)(-log(pos / neg));
    }
}

// ---------------------------------------------------------------------------
extern "C" void kernel_launch(void* const* d_in, const int* in_sizes, int n_in,
                              void* d_out, int out_size)
{
    const float* img = (const float*)d_in[0];  // bg_img_feature [256,1024]
    const float* fg  = (const float*)d_in[1];  // fg_pro_feature [256,1024]
    const float* pro = (const float*)d_in[2];  // bg_pro_feature [256,512,1024]

    fused_kernel<<<NBLK, 256>>>(img, fg, pro);

    // Launch the reduce with Programmatic Dependent Launch so its launch
    // overhead overlaps the streamer's drain.
    cudaLaunchConfig_t cfg = {};
    cfg.gridDim  = dim3(RBLK, 1, 1);
    cfg.blockDim = dim3(256, 1, 1);
    cfg.dynamicSmemBytes = 0;
    cudaLaunchAttribute attrs[1];
    attrs[0].id = cudaLaunchAttributeProgrammaticStreamSerialization;
    attrs[0].val.programmaticStreamSerializationAllowed = 1;
    cfg.attrs = attrs;
    cfg.numAttrs = 1;

    float* out = (float*)d_out;
    cudaLaunchKernelEx(&cfg, reduce_kernel, out);
}

// round 10
// speedup vs baseline: 1.1330x; 1.0273x over previous
#include <cuda_runtime.h>
#include <math.h>

// Problem constants (fixed by the dataset): B=256, K=512, D=1024
#define B_SZ 256
#define K_SZ 512
#define D_SZ 1024
#define INV_T (1.0f / 0.07f)

#define K_PER_BLOCK 8                      // 8 warps per block, one k per warp
#define BLOCKS_PER_B (K_SZ / K_PER_BLOCK)  // 64
#define NBLK (B_SZ * BLOCKS_PER_B)         // 16384

// Scratch (no cudaMalloc allowed; zero-initialized)
__device__ float g_fg_per_b[B_SZ];       // exp(fg_logit / T) per sample
__device__ float g_part[NBLK];           // per-block partial sums
__device__ float g_bsum[B_SZ];           // per-sample folded sums
__device__ unsigned g_cnt_b[B_SZ];       // per-sample arrival counters
__device__ unsigned g_cnt_all;           // finisher counter

__device__ __forceinline__ void release_add(unsigned* ctr) {
    unsigned r;
    asm volatile("atom.release.gpu.global.add.u32 %0, [%1], %2;"
                 : "=r"(r) : "l"(ctr), "r"(1u) : "memory");
}
__device__ __forceinline__ unsigned acq_rel_add(unsigned* ctr) {
    unsigned r;
    asm volatile("atom.acq_rel.gpu.global.add.u32 %0, [%1], %2;"
                 : "=r"(r) : "l"(ctr), "r"(1u) : "memory");
    return r;
}
__device__ __forceinline__ unsigned load_acquire(const unsigned* p) {
    unsigned r;
    asm volatile("ld.acquire.gpu.global.u32 %0, [%1];" : "=r"(r) : "l"(p) : "memory");
    return r;
}

// ---------------------------------------------------------------------------
// Kernel A: the proven streamer (R9 body). Adds ONE release-atomic per block
// (t0 only, no extra syncs) and fires launch_dependents at the TOP so the
// consumer can overlap per-sample folding with ongoing streaming.
// grid = 16384, block = 256
// ---------------------------------------------------------------------------
__global__ void __launch_bounds__(256) fused_kernel(
    const float* __restrict__ img,
    const float* __restrict__ fg,
    const float* __restrict__ pro)
{
    __shared__ float4 s_img[256];   // 4 KB: the img row
    __shared__ float  s_ss[8];
    __shared__ float  s_fg[8];
    __shared__ float  s_part[8];

    const int blk  = blockIdx.x;
    const int b    = blk >> 6;          // blk / BLOCKS_PER_B
    const int kgrp = blk & 63;          // blk % BLOCKS_PER_B
    const int t    = threadIdx.x;
    const int w    = t >> 5;
    const int l    = t & 31;

    // PDL: consumer is gated by data counters, not grid completion — let it
    // launch as early as possible.
    if (t == 0)
        asm volatile("griddepcontrol.launch_dependents;");

    // ---- load img row into smem + sum of squares ----
    float4 v = ((const float4*)(img + (size_t)b * D_SZ))[t];
    s_img[t] = v;

    float ss = v.x * v.x + v.y * v.y + v.z * v.z + v.w * v.w;
    #pragma unroll
    for (int o = 16; o > 0; o >>= 1)
        ss += __shfl_xor_sync(0xFFFFFFFFu, ss, o);
    if (l == 0) s_ss[w] = ss;
    __syncthreads();

    float tss = 0.f;
    #pragma unroll
    for (int i = 0; i < 8; i++) tss += s_ss[i];
    const float inv = 1.0f / sqrtf(tss);

    // ---- fg dot: only in the first block of each sample ----
    if (kgrp == 0) {
        float4 f = ((const float4*)(fg + (size_t)b * D_SZ))[t];
        float fd = v.x * f.x + v.y * f.y + v.z * f.z + v.w * f.w;
        #pragma unroll
        for (int o = 16; o > 0; o >>= 1)
            fd += __shfl_xor_sync(0xFFFFFFFFu, fd, o);
        if (l == 0) s_fg[w] = fd;
        __syncthreads();
        if (t == 0) {
            float tfd = 0.f;
            #pragma unroll
            for (int i = 0; i < 8; i++) tfd += s_fg[i];
            g_fg_per_b[b] = expf(tfd * inv * INV_T);   // ordered by release below
        }
    }

    // ---- each warp: one (b,k) dot, pro streamed from DRAM ----
    const int k = (kgrp << 3) + w;
    const float4* p4 = (const float4*)(pro + ((size_t)b * K_SZ + k) * D_SZ);

    float4 p[8];
    #pragma unroll
    for (int j = 0; j < 8; j++)
        p[j] = __ldcs(p4 + j * 32 + l);     // 8 independent streaming LDG.128

    float acc = 0.f;
    #pragma unroll
    for (int j = 0; j < 8; j++) {
        float4 a = s_img[j * 32 + l];
        acc += a.x * p[j].x + a.y * p[j].y + a.z * p[j].z + a.w * p[j].w;
    }

    #pragma unroll
    for (int o = 16; o > 0; o >>= 1)
        acc += __shfl_xor_sync(0xFFFFFFFFu, acc, o);
    if (l == 0) s_part[w] = expf(acc * inv * INV_T);
    __syncthreads();

    if (t == 0) {
        float tsum = 0.f;
        #pragma unroll
        for (int i = 0; i < 8; i++) tsum += s_part[i];
        g_part[blk] = tsum;               // fixed order: deterministic
        release_add(&g_cnt_b[b]);         // publish: partials (+ fg) visible
    }
}

// ---------------------------------------------------------------------------
// Kernel B: 256 one-warp blocks, PDL-launched early (no griddepcontrol.wait).
// Block b spin-sleeps until g_cnt_b[b]==64, folds its 64 partials (overlapped
// with A's remaining streaming), then the 256th finisher folds everything.
// grid = 256, block = 32
// ---------------------------------------------------------------------------
__global__ void __launch_bounds__(32) reduce_kernel(float* __restrict__ out)
{
    const int b = blockIdx.x;
    const int l = threadIdx.x;

    // ---- wait for this sample's 64 partials (all lanes poll: each gets
    //      its own acquire, so subsequent loads are ordered per-lane) ----
    while (load_acquire(&g_cnt_b[b]) != (unsigned)BLOCKS_PER_B)
        __nanosleep(128);

    // ---- fold 64 partials (fixed order) ----
    float a = g_part[(b << 6) + l] + g_part[(b << 6) + 32 + l];
    #pragma unroll
    for (int o = 16; o > 0; o >>= 1)
        a += __shfl_xor_sync(0xFFFFFFFFu, a, o);

    __shared__ int s_last;
    if (l == 0) {
        g_bsum[b]  = a;
        g_cnt_b[b] = 0;                        // reset for next graph replay
        unsigned r = acq_rel_add(&g_cnt_all);  // release g_bsum, acquire others
        s_last = (r == (unsigned)(B_SZ - 1));
    }
    __syncwarp();
    // broadcast finisher decision to the warp
    int last = __shfl_sync(0xFFFFFFFFu, s_last, 0);
    if (!last) return;

    // ---- finisher: fold 256 b-sums + 256 fg terms (fixed order) ----
    if (l == 0) g_cnt_all = 0;                 // reset for next graph replay

    double a2 = 0.0, f2 = 0.0;
    #pragma unroll
    for (int j = 0; j < 8; j++) {              // 8 values per lane
        a2 += (double)g_bsum[j * 32 + l];
        f2 += (double)g_fg_per_b[j * 32 + l];
    }
    #pragma unroll
    for (int o = 16; o > 0; o >>= 1) {
        a2 += __shfl_xor_sync(0xFFFFFFFFu, a2, o);
        f2 += __shfl_xor_sync(0xFFFFFFFFu, f2, o);
    }

    if (l == 0) {
        double pos = a2 / (double)K_SZ;        // sum_b mean_k exp(...)
        double neg = pos + f2;
        out[0] = (float)(-log(pos / neg));
    }
}

// ---------------------------------------------------------------------------
extern "C" void kernel_launch(void* const* d_in, const int* in_sizes, int n_in,
                              void* d_out, int out_size)
{
    const float* img = (const float*)d_in[0];  // bg_img_feature [256,1024]
    const float* fg  = (const float*)d_in[1];  // fg_pro_feature [256,1024]
    const float* pro = (const float*)d_in[2];  // bg_pro_feature [256,512,1024]

    fused_kernel<<<NBLK, 256>>>(img, fg, pro);

    // PDL: reduce launches while the streamer runs; it self-synchronizes on
    // the per-sample counters (never calls griddepcontrol.wait).
    cudaLaunchConfig_t cfg = {};
    cfg.gridDim  = dim3(B_SZ, 1, 1);
    cfg.blockDim = dim3(32, 1, 1);
    cfg.dynamicSmemBytes = 0;
    cudaLaunchAttribute attrs[1];
    attrs[0].id = cudaLaunchAttributeProgrammaticStreamSerialization;
    attrs[0].val.programmaticStreamSerializationAllowed = 1;
    cfg.attrs = attrs;
    cfg.numAttrs = 1;

    float* out = (float*)d_out;
    cudaLaunchKernelEx(&cfg, reduce_kernel, out);
}